// round 15
// baseline (speedup 1.0000x reference)
#include <cuda_runtime.h>

#define BATCH   16
#define KPTS    2048
#define NPOINT  2048

#define TPB_A   128
#define IBLK    2
#define ICHUNK  (TPB_A * IBLK)        // 256 i-points per CTA (2 per thread)
#define NI_CH   (KPTS / ICHUNK)       // 8
#define JS      16                    // j-chunks
#define JCH     (KPTS / JS)           // 128

#define TPB_SEL 256
#define NSEL    (KPTS / TPB_SEL)      // 8 CTAs per batch
#define CPAD    132                   // floats per chunk row in A2 smem (128+4)

#define TPB_B1  1024
#define NWARP_B (TPB_B1 / 32)
#define ELEMS_B (KPTS / TPB_B1)
#define FLT_BIG 3.402823466e38f

typedef unsigned long long u64;

// per-(batch, chunk, i) chunk-min distance (d' domain, self excluded)
__device__ float g_min[BATCH * JS * KPTS];
__device__ float g_value[BATCH * KPTS];

// ---- packed f32x2 helpers ---------------------------------------------------
__device__ __forceinline__ u64 f2pack(float lo, float hi) {
    u64 r; asm("mov.b64 %0, {%1, %2};" : "=l"(r) : "f"(lo), "f"(hi)); return r;
}
__device__ __forceinline__ u64 fma2(u64 a, u64 b, u64 c) {
    u64 d; asm("fma.rn.f32x2 %0, %1, %2, %3;" : "=l"(d) : "l"(a), "l"(b), "l"(c));
    return d;
}
__device__ __forceinline__ void f2unpack(u64 v, float& lo, float& hi) {
    asm("mov.b64 {%0, %1}, %2;" : "=f"(lo), "=f"(hi) : "l"(v));
}
__device__ __forceinline__ void s_top2(float c, float& m1, float& m2) {
    float t = fmaxf(m1, c); m1 = fminf(m1, c); m2 = fminf(m2, t);
}
__device__ __forceinline__ void s_top3(float c, float& m1, float& m2, float& m3) {
    float t1 = fmaxf(m1, c); m1 = fminf(m1, c);
    float t2 = fmaxf(m2, t1); m2 = fminf(m2, t1); m3 = fminf(m3, t2);
}

// ---- A1 chunk scan: 2 accumulators, min-only (top-2 for self acc) -----------
// SELF in {-1,0,1}: which accumulator's self point lies in this chunk.
// Self acc tracks top-2 (self included); union-2nd == min excluding self.
template<int SELF>
__device__ __forceinline__ void scan_min2(
    const ulonglong2* __restrict__ px2, const ulonglong2* __restrict__ py2,
    const ulonglong2* __restrict__ pz2, const ulonglong2* __restrict__ pw2,
    u64 ax0, u64 ay0, u64 az0, u64 ax1, u64 ay1, u64 az1,
    float& o0, float& o1)
{
    float a1 = FLT_BIG, a2 = FLT_BIG, a3 = FLT_BIG, a4 = FLT_BIG;
    float b1 = FLT_BIG, b2 = FLT_BIG, b3 = FLT_BIG, b4 = FLT_BIG;

    #pragma unroll 8
    for (int q = 0; q < JCH / 4; ++q) {
        ulonglong2 X = px2[q], Y = py2[q], Z = pz2[q], W = pw2[q];

        u64 d01 = fma2(Z.x, az0, fma2(Y.x, ay0, fma2(X.x, ax0, W.x)));
        u64 d23 = fma2(Z.y, az0, fma2(Y.y, ay0, fma2(X.y, ax0, W.y)));
        float l0, h0, l1, h1;
        f2unpack(d01, l0, h0); f2unpack(d23, l1, h1);
        if (SELF == 0) {
            s_top2(l0, a1, a2); s_top2(h0, a3, a4);
            s_top2(l1, a1, a2); s_top2(h1, a3, a4);
        } else {
            a1 = fminf(a1, fminf(l0, l1));
            a3 = fminf(a3, fminf(h0, h1));
        }

        u64 e01 = fma2(Z.x, az1, fma2(Y.x, ay1, fma2(X.x, ax1, W.x)));
        u64 e23 = fma2(Z.y, az1, fma2(Y.y, ay1, fma2(X.y, ax1, W.y)));
        f2unpack(e01, l0, h0); f2unpack(e23, l1, h1);
        if (SELF == 1) {
            s_top2(l0, b1, b2); s_top2(h0, b3, b4);
            s_top2(l1, b1, b2); s_top2(h1, b3, b4);
        } else {
            b1 = fminf(b1, fminf(l0, l1));
            b3 = fminf(b3, fminf(h0, h1));
        }
    }

    if (SELF == 0)   // union 2nd-smallest of sorted pairs (a1,a2),(a3,a4)
        o0 = fminf(fmaxf(a1, a3), fminf(a2, a4));
    else
        o0 = fminf(a1, a3);
    if (SELF == 1)
        o1 = fminf(fmaxf(b1, b3), fminf(b2, b4));
    else
        o1 = fminf(b1, b3);
}

// ---------------------------------------------------------------------------
// Kernel A1: per-(batch, chunk, i) chunk-min. grid (8, 16, 16) = 2048 CTAs
// x 128 thr. __launch_bounds__(128, 12): regs <= ~42 -> 12 CTAs/SM =
// 48 warps/SM; 2048 CTAs fit the 148*12 = 1776... (1.15 waves, fine-grained).
// i0 = ci*256+tid lives in chunk 2*ci; i1 = i0+128 in chunk 2*ci+1.
// ---------------------------------------------------------------------------
__global__ __launch_bounds__(TPB_A, 12)
void sor_chunkmin_kernel(const float* __restrict__ x) {
    __shared__ __align__(16) float spx[JCH];
    __shared__ __align__(16) float spy[JCH];
    __shared__ __align__(16) float spz[JCH];
    __shared__ __align__(16) float spw[JCH];

    const int b   = blockIdx.z;
    const int ci  = blockIdx.x;
    const int cj  = blockIdx.y;
    const int tid = threadIdx.x;
    const float* __restrict__ xb = x + b * 3 * KPTS;

    {   // stage j-chunk in SoA (JCH == TPB_A)
        int g = cj * JCH + tid;
        float px = xb[g];
        float py = xb[KPTS + g];
        float pz = xb[2 * KPTS + g];
        float sq = __fadd_rn(__fadd_rn(__fmul_rn(px, px), __fmul_rn(py, py)),
                             __fmul_rn(pz, pz));
        spx[tid] = px; spy[tid] = py; spz[tid] = pz; spw[tid] = sq;
    }
    __syncthreads();

    const int i0 = ci * ICHUNK + tid;
    const int i1 = i0 + TPB_A;

    float x0 = xb[i0], y0 = xb[KPTS + i0], z0 = xb[2 * KPTS + i0];
    float x1 = xb[i1], y1 = xb[KPTS + i1], z1 = xb[2 * KPTS + i1];
    const u64 ax0 = f2pack(-2.0f * x0, -2.0f * x0);
    const u64 ay0 = f2pack(-2.0f * y0, -2.0f * y0);
    const u64 az0 = f2pack(-2.0f * z0, -2.0f * z0);
    const u64 ax1 = f2pack(-2.0f * x1, -2.0f * x1);
    const u64 ay1 = f2pack(-2.0f * y1, -2.0f * y1);
    const u64 az1 = f2pack(-2.0f * z1, -2.0f * z1);

    const ulonglong2* px2 = reinterpret_cast<const ulonglong2*>(spx);
    const ulonglong2* py2 = reinterpret_cast<const ulonglong2*>(spy);
    const ulonglong2* pz2 = reinterpret_cast<const ulonglong2*>(spz);
    const ulonglong2* pw2 = reinterpret_cast<const ulonglong2*>(spw);

    float o0, o1;
    if (cj == 2 * ci)
        scan_min2<0>(px2, py2, pz2, pw2, ax0, ay0, az0, ax1, ay1, az1, o0, o1);
    else if (cj == 2 * ci + 1)
        scan_min2<1>(px2, py2, pz2, pw2, ax0, ay0, az0, ax1, ay1, az1, o0, o1);
    else
        scan_min2<-1>(px2, py2, pz2, pw2, ax0, ay0, az0, ax1, ay1, az1, o0, o1);

    float* __restrict__ gm = g_min + (b * JS + cj) * KPTS;
    gm[i0] = o0;
    gm[i1] = o1;
}

// ---------------------------------------------------------------------------
// Kernel A2: exact top-2 recovery. grid (8, 16) = 128 CTAs x 256 thr.
// Each CTA stages the WHOLE batch SoA (33KB smem) and handles 256 points:
// argmin chunk cstar + 2nd-smallest chunk-min r2, then rescan cstar (top-3,
// self included) from smem.
//   cstar == own chunk: nn1 = R2, nn2 = min(R3, r2)   (R1 = self, dropped)
//   else:               nn1 = R1, nn2 = min(R2, r2)
// Exact: any candidate outside cstar is >= its chunk min >= r2.
// ---------------------------------------------------------------------------
__global__ __launch_bounds__(TPB_SEL)
void sor_select_kernel(const float* __restrict__ x) {
    __shared__ __align__(16) float sxp[JS * CPAD];
    __shared__ __align__(16) float syp[JS * CPAD];
    __shared__ __align__(16) float szp[JS * CPAD];
    __shared__ __align__(16) float swp[JS * CPAD];

    const int b   = blockIdx.y;
    const int tid = threadIdx.x;
    const int i   = blockIdx.x * TPB_SEL + tid;
    const float* __restrict__ xb = x + b * 3 * KPTS;

    for (int idx = tid; idx < KPTS; idx += TPB_SEL) {
        int c = idx >> 7, e = idx & 127;
        float px = xb[idx];
        float py = xb[KPTS + idx];
        float pz = xb[2 * KPTS + idx];
        float sq = __fadd_rn(__fadd_rn(__fmul_rn(px, px), __fmul_rn(py, py)),
                             __fmul_rn(pz, pz));
        int off = c * CPAD + e;
        sxp[off] = px; syp[off] = py; szp[off] = pz; swp[off] = sq;
    }
    __syncthreads();

    // ---- chunk mins -> m1, cstar, r2 ----
    float m1 = FLT_BIG, r2 = FLT_BIG;
    int cstar = 0;
    #pragma unroll
    for (int c = 0; c < JS; ++c) {
        float v = g_min[(b * JS + c) * KPTS + i];
        if (v < m1) { r2 = m1; m1 = v; cstar = c; }
        else        { r2 = fminf(r2, v); }
    }

    // ---- own point data ----
    const int sc = i >> 7;
    const int se = i & 127;
    const int ob = sc * CPAD + se;
    const float xi = sxp[ob], yi = syp[ob], zi = szp[ob], si = swp[ob];
    const u64 ax = f2pack(-2.0f * xi, -2.0f * xi);
    const u64 ay = f2pack(-2.0f * yi, -2.0f * yi);
    const u64 az = f2pack(-2.0f * zi, -2.0f * zi);

    // ---- rescan chunk cstar with top-3 dual chains (self included) ----
    const ulonglong2* X = reinterpret_cast<const ulonglong2*>(sxp + cstar * CPAD);
    const ulonglong2* Y = reinterpret_cast<const ulonglong2*>(syp + cstar * CPAD);
    const ulonglong2* Z = reinterpret_cast<const ulonglong2*>(szp + cstar * CPAD);
    const ulonglong2* W = reinterpret_cast<const ulonglong2*>(swp + cstar * CPAD);

    float C[6] = {FLT_BIG, FLT_BIG, FLT_BIG, FLT_BIG, FLT_BIG, FLT_BIG};
    #pragma unroll 4
    for (int q = 0; q < JCH / 4; ++q) {
        ulonglong2 Xv = X[q], Yv = Y[q], Zv = Z[q], Wv = W[q];
        u64 d01 = fma2(Zv.x, az, fma2(Yv.x, ay, fma2(Xv.x, ax, Wv.x)));
        u64 d23 = fma2(Zv.y, az, fma2(Yv.y, ay, fma2(Xv.y, ax, Wv.y)));
        float l0, h0, l1, h1;
        f2unpack(d01, l0, h0); f2unpack(d23, l1, h1);
        s_top3(l0, C[0], C[1], C[2]); s_top3(h0, C[3], C[4], C[5]);
        s_top3(l1, C[0], C[1], C[2]); s_top3(h1, C[3], C[4], C[5]);
    }
    float R1 = C[0], R2 = C[1], R3 = C[2];
    s_top3(C[3], R1, R2, R3);
    s_top3(C[4], R1, R2, R3);
    s_top3(C[5], R1, R2, R3);

    float nn1, nn2;
    if (cstar == sc) { nn1 = R2; nn2 = fminf(R3, r2); }  // R1 == self, dropped
    else             { nn1 = R1; nn2 = fminf(R2, r2); }

    g_value[b * KPTS + i] =
        (__fadd_rn(nn1, si) + __fadd_rn(nn2, si)) * 0.5f;
}

// ---------------------------------------------------------------------------
// Kernel B1: per-batch stats + stable compaction + tiled gather (unchanged).
// ---------------------------------------------------------------------------
__global__ __launch_bounds__(TPB_B1)
void sor_compact_gather_kernel(const float* __restrict__ x,
                               float* __restrict__ out) {
    __shared__ float sx[KPTS];
    __shared__ float sy[KPTS];
    __shared__ float sz[KPTS];
    __shared__ float sval[KPTS];
    __shared__ int   skept[KPTS];
    __shared__ float red[NWARP_B];
    __shared__ int   wofs[NWARP_B];
    __shared__ float s_mean, s_thr;
    __shared__ int   s_n;

    const int b    = blockIdx.x;
    const int tid  = threadIdx.x;
    const int lane = tid & 31;
    const int warp = tid >> 5;
    const float* __restrict__ xb = x + b * 3 * KPTS;
    float* __restrict__ ob = out + b * 3 * KPTS;

    #pragma unroll
    for (int t = tid; t < KPTS; t += TPB_B1) {
        sx[t]   = xb[t];
        sy[t]   = xb[KPTS + t];
        sz[t]   = xb[2 * KPTS + t];
        sval[t] = g_value[b * KPTS + t];
    }
    __syncthreads();

    // ---- mean ----
    float s = 0.0f;
    #pragma unroll
    for (int t = tid; t < KPTS; t += TPB_B1) s += sval[t];
    #pragma unroll
    for (int o = 16; o; o >>= 1) s += __shfl_xor_sync(0xffffffffu, s, o);
    if (lane == 0) red[warp] = s;
    __syncthreads();
    if (warp == 0) {
        float v = red[lane];
        #pragma unroll
        for (int o = 16; o; o >>= 1) v += __shfl_xor_sync(0xffffffffu, v, o);
        if (lane == 0) s_mean = v * (1.0f / (float)KPTS);
    }
    __syncthreads();
    const float mean = s_mean;

    // ---- std (ddof = 1) ----
    float s2 = 0.0f;
    #pragma unroll
    for (int t = tid; t < KPTS; t += TPB_B1) {
        float d = sval[t] - mean;
        s2 = __fmaf_rn(d, d, s2);
    }
    #pragma unroll
    for (int o = 16; o; o >>= 1) s2 += __shfl_xor_sync(0xffffffffu, s2, o);
    if (lane == 0) red[warp] = s2;
    __syncthreads();
    if (warp == 0) {
        float v = red[lane];
        #pragma unroll
        for (int o = 16; o; o >>= 1) v += __shfl_xor_sync(0xffffffffu, v, o);
        if (lane == 0) {
            float var = v / (float)(KPTS - 1);
            s_thr = __fadd_rn(s_mean, __fmul_rn(1.1f, sqrtf(var)));
        }
    }
    __syncthreads();
    const float thr = s_thr;

    // ---- stable compaction ----
    const int base_t = tid * ELEMS_B;
    unsigned mbits = 0;
    int c = 0;
    #pragma unroll
    for (int u = 0; u < ELEMS_B; ++u) {
        bool m = sval[base_t + u] <= thr;
        mbits |= (unsigned)m << u;
        c += (int)m;
    }
    int v = c;
    #pragma unroll
    for (int o = 1; o < 32; o <<= 1) {
        int t2 = __shfl_up_sync(0xffffffffu, v, o);
        if (lane >= o) v += t2;
    }
    if (lane == 31) wofs[warp] = v;
    __syncthreads();
    if (warp == 0) {
        int wv = wofs[lane];
        int inc = wv;
        #pragma unroll
        for (int o = 1; o < 32; o <<= 1) {
            int t3 = __shfl_up_sync(0xffffffffu, inc, o);
            if (lane >= o) inc += t3;
        }
        wofs[lane] = inc - wv;
        if (lane == 31) s_n = inc;
    }
    __syncthreads();
    int pos = (v - c) + wofs[warp];
    #pragma unroll
    for (int u = 0; u < ELEMS_B; ++u) {
        if ((mbits >> u) & 1u) skept[pos++] = base_t + u;
    }
    __syncthreads();

    // ---- tiled gather ----
    const int n = s_n;
    #pragma unroll
    for (int j = tid; j < NPOINT; j += TPB_B1) {
        int p = (j < n) ? j : (j % n);
        int idx = skept[p];
        ob[j]            = sx[idx];
        ob[KPTS + j]     = sy[idx];
        ob[2 * KPTS + j] = sz[idx];
    }
}

extern "C" void kernel_launch(void* const* d_in, const int* in_sizes, int n_in,
                              void* d_out, int out_size) {
    (void)in_sizes; (void)n_in; (void)out_size;
    const float* x = (const float*)d_in[0];
    float* out = (float*)d_out;

    sor_chunkmin_kernel<<<dim3(NI_CH, JS, BATCH), TPB_A>>>(x);
    sor_select_kernel<<<dim3(NSEL, BATCH), TPB_SEL>>>(x);
    sor_compact_gather_kernel<<<BATCH, TPB_B1>>>(x, out);
}

// round 16
// speedup vs baseline: 1.0826x; 1.0826x over previous
#include <cuda_runtime.h>

#define BATCH   16
#define KPTS    2048
#define NPOINT  2048

#define TPB_A   128
#define IBLK    4
#define ICHUNK  (TPB_A * IBLK)        // 512 i-points per CTA (4 per thread)
#define NI_CH   (KPTS / ICHUNK)       // 4
#define JS      16                    // j-chunks
#define JCH     (KPTS / JS)           // 128

#define TPB_SEL 256
#define NSEL    (KPTS / TPB_SEL)      // 8 CTAs per batch
#define CPAD    132                   // floats per chunk row in A2 smem (128+4)

#define TPB_B1  512
#define NWARP_B (TPB_B1 / 32)         // 16
#define ELEMS_B (KPTS / TPB_B1)       // 4
#define FLT_BIG 3.402823466e38f

typedef unsigned long long u64;

// per-(batch, chunk, i) chunk-min distance (d' domain, self excluded)
__device__ float g_min[BATCH * JS * KPTS];
__device__ float g_value[BATCH * KPTS];
__device__ float g_sum[BATCH * NSEL];    // per-A2-CTA partial sums of value

// ---- packed f32x2 helpers ---------------------------------------------------
__device__ __forceinline__ u64 f2pack(float lo, float hi) {
    u64 r; asm("mov.b64 %0, {%1, %2};" : "=l"(r) : "f"(lo), "f"(hi)); return r;
}
__device__ __forceinline__ u64 fma2(u64 a, u64 b, u64 c) {
    u64 d; asm("fma.rn.f32x2 %0, %1, %2, %3;" : "=l"(d) : "l"(a), "l"(b), "l"(c));
    return d;
}
__device__ __forceinline__ void f2unpack(u64 v, float& lo, float& hi) {
    asm("mov.b64 {%0, %1}, %2;" : "=f"(lo), "=f"(hi) : "l"(v));
}
__device__ __forceinline__ void s_top2(float c, float& m1, float& m2) {
    float t = fmaxf(m1, c); m1 = fminf(m1, c); m2 = fminf(m2, t);
}
__device__ __forceinline__ void s_top3(float c, float& m1, float& m2, float& m3) {
    float t1 = fmaxf(m1, c); m1 = fminf(m1, c);
    float t2 = fmaxf(m2, t1); m2 = fminf(m2, t1); m3 = fminf(m3, t2);
}

// ---- A1 chunk scan: 4 accumulators, min-only, double-buffered LDS -----------
// SELF in {-1,0,1,2,3}: which accumulator's self point lies in this chunk.
// The self acc tracks top-2 (self included) and reports m2 == self-free chunk
// min (self distance is provably the chunk min). Others track running min.
template<int SELF>
__device__ __forceinline__ void scan_min4(
    const ulonglong2* __restrict__ px2, const ulonglong2* __restrict__ py2,
    const ulonglong2* __restrict__ pz2, const ulonglong2* __restrict__ pw2,
    const u64* ax, const u64* ay, const u64* az,
    float* out)
{
    float a1[IBLK], a2[IBLK], a3[IBLK], a4[IBLK];
    #pragma unroll
    for (int k = 0; k < IBLK; ++k) {
        a1[k] = FLT_BIG; a2[k] = FLT_BIG; a3[k] = FLT_BIG; a4[k] = FLT_BIG;
    }

    // prefetch q=0
    ulonglong2 X = px2[0], Y = py2[0], Z = pz2[0], W = pw2[0];

    #pragma unroll 4
    for (int q = 0; q < JCH / 4; ++q) {
        // prefetch q+1 (clamped; the duplicate last load is harmless)
        const int qn = (q + 1 < JCH / 4) ? q + 1 : q;
        ulonglong2 Xn = px2[qn], Yn = py2[qn], Zn = pz2[qn], Wn = pw2[qn];

        #pragma unroll
        for (int k = 0; k < IBLK; ++k) {
            u64 d01 = fma2(Z.x, az[k], fma2(Y.x, ay[k], fma2(X.x, ax[k], W.x)));
            u64 d23 = fma2(Z.y, az[k], fma2(Y.y, ay[k], fma2(X.y, ax[k], W.y)));
            float l0, h0, l1, h1;
            f2unpack(d01, l0, h0); f2unpack(d23, l1, h1);
            if (SELF == k) {
                s_top2(l0, a1[k], a2[k]); s_top2(h0, a3[k], a4[k]);
                s_top2(l1, a1[k], a2[k]); s_top2(h1, a3[k], a4[k]);
            } else {
                a1[k] = fminf(a1[k], fminf(l0, l1));
                a3[k] = fminf(a3[k], fminf(h0, h1));
            }
        }

        X = Xn; Y = Yn; Z = Zn; W = Wn;
    }

    #pragma unroll
    for (int k = 0; k < IBLK; ++k) {
        if (SELF == k)   // union 2nd-smallest of sorted pairs (a1,a2),(a3,a4)
            out[k] = fminf(fmaxf(a1[k], a3[k]), fminf(a2[k], a4[k]));
        else
            out[k] = fminf(a1[k], a3[k]);
    }
}

// ---------------------------------------------------------------------------
// Kernel A1: per-(batch, chunk, i) chunk-min. grid (4, 16, 16) x 128 thr.
// __launch_bounds__(128, 7): regs <= 73 -> 7 CTAs/SM * 148 = 1036 >= 1024
// CTAs: whole grid resident in ONE wave, with prefetch headroom.
// ---------------------------------------------------------------------------
__global__ __launch_bounds__(TPB_A, 7)
void sor_chunkmin_kernel(const float* __restrict__ x) {
    __shared__ __align__(16) float spx[JCH];
    __shared__ __align__(16) float spy[JCH];
    __shared__ __align__(16) float spz[JCH];
    __shared__ __align__(16) float spw[JCH];

    const int b   = blockIdx.z;
    const int ci  = blockIdx.x;
    const int cj  = blockIdx.y;
    const int tid = threadIdx.x;
    const float* __restrict__ xb = x + b * 3 * KPTS;

    {   // stage j-chunk in SoA (JCH == TPB_A)
        int g = cj * JCH + tid;
        float px = xb[g];
        float py = xb[KPTS + g];
        float pz = xb[2 * KPTS + g];
        float sq = __fadd_rn(__fadd_rn(__fmul_rn(px, px), __fmul_rn(py, py)),
                             __fmul_rn(pz, pz));
        spx[tid] = px; spy[tid] = py; spz[tid] = pz; spw[tid] = sq;
    }
    __syncthreads();

    u64 ax[IBLK], ay[IBLK], az[IBLK];
    int ibase = ci * ICHUNK + tid;
    #pragma unroll
    for (int k = 0; k < IBLK; ++k) {
        int ik = ibase + k * TPB_A;
        float xv = xb[ik], yv = xb[KPTS + ik], zv = xb[2 * KPTS + ik];
        ax[k] = f2pack(-2.0f * xv, -2.0f * xv);
        ay[k] = f2pack(-2.0f * yv, -2.0f * yv);
        az[k] = f2pack(-2.0f * zv, -2.0f * zv);
    }

    const ulonglong2* px2 = reinterpret_cast<const ulonglong2*>(spx);
    const ulonglong2* py2 = reinterpret_cast<const ulonglong2*>(spy);
    const ulonglong2* pz2 = reinterpret_cast<const ulonglong2*>(spz);
    const ulonglong2* pw2 = reinterpret_cast<const ulonglong2*>(spw);

    float out[IBLK];
    const int selfk = cj - 4 * ci;    // in [0,4) iff some acc's self is here
    switch (selfk) {
        case 0:  scan_min4<0>(px2, py2, pz2, pw2, ax, ay, az, out); break;
        case 1:  scan_min4<1>(px2, py2, pz2, pw2, ax, ay, az, out); break;
        case 2:  scan_min4<2>(px2, py2, pz2, pw2, ax, ay, az, out); break;
        case 3:  scan_min4<3>(px2, py2, pz2, pw2, ax, ay, az, out); break;
        default: scan_min4<-1>(px2, py2, pz2, pw2, ax, ay, az, out); break;
    }

    float* __restrict__ gm = g_min + (b * JS + cj) * KPTS;
    #pragma unroll
    for (int k = 0; k < IBLK; ++k) gm[ibase + k * TPB_A] = out[k];
}

// ---------------------------------------------------------------------------
// Kernel A2: exact top-2 recovery + per-CTA partial sum of value.
// grid (8, 16) = 128 CTAs x 256 thr. Each CTA stages the WHOLE batch SoA
// (33KB smem) and handles 256 points: argmin chunk cstar + 2nd-smallest
// chunk-min r2, then rescan cstar (top-3, self included) from smem.
//   cstar == own chunk: nn1 = R2, nn2 = min(R3, r2)   (R1 = self, dropped)
//   else:               nn1 = R1, nn2 = min(R2, r2)
// Exact: any candidate outside cstar is >= its chunk min >= r2.
// Partial sum: deterministic shuffle tree + fixed-order 8-warp combine.
// ---------------------------------------------------------------------------
__global__ __launch_bounds__(TPB_SEL)
void sor_select_kernel(const float* __restrict__ x) {
    __shared__ __align__(16) float sxp[JS * CPAD];
    __shared__ __align__(16) float syp[JS * CPAD];
    __shared__ __align__(16) float szp[JS * CPAD];
    __shared__ __align__(16) float swp[JS * CPAD];
    __shared__ float sred[TPB_SEL / 32];

    const int b   = blockIdx.y;
    const int tid = threadIdx.x;
    const int i   = blockIdx.x * TPB_SEL + tid;
    const float* __restrict__ xb = x + b * 3 * KPTS;

    for (int idx = tid; idx < KPTS; idx += TPB_SEL) {
        int c = idx >> 7, e = idx & 127;
        float px = xb[idx];
        float py = xb[KPTS + idx];
        float pz = xb[2 * KPTS + idx];
        float sq = __fadd_rn(__fadd_rn(__fmul_rn(px, px), __fmul_rn(py, py)),
                             __fmul_rn(pz, pz));
        int off = c * CPAD + e;
        sxp[off] = px; syp[off] = py; szp[off] = pz; swp[off] = sq;
    }
    __syncthreads();

    // ---- chunk mins -> m1, cstar, r2 ----
    float m1 = FLT_BIG, r2 = FLT_BIG;
    int cstar = 0;
    #pragma unroll
    for (int c = 0; c < JS; ++c) {
        float v = g_min[(b * JS + c) * KPTS + i];
        if (v < m1) { r2 = m1; m1 = v; cstar = c; }
        else        { r2 = fminf(r2, v); }
    }

    // ---- own point data ----
    const int sc = i >> 7;
    const int se = i & 127;
    const int ob = sc * CPAD + se;
    const float xi = sxp[ob], yi = syp[ob], zi = szp[ob], si = swp[ob];
    const u64 ax = f2pack(-2.0f * xi, -2.0f * xi);
    const u64 ay = f2pack(-2.0f * yi, -2.0f * yi);
    const u64 az = f2pack(-2.0f * zi, -2.0f * zi);

    // ---- rescan chunk cstar with top-3 dual chains (self included) ----
    const ulonglong2* X = reinterpret_cast<const ulonglong2*>(sxp + cstar * CPAD);
    const ulonglong2* Y = reinterpret_cast<const ulonglong2*>(syp + cstar * CPAD);
    const ulonglong2* Z = reinterpret_cast<const ulonglong2*>(szp + cstar * CPAD);
    const ulonglong2* W = reinterpret_cast<const ulonglong2*>(swp + cstar * CPAD);

    float C[6] = {FLT_BIG, FLT_BIG, FLT_BIG, FLT_BIG, FLT_BIG, FLT_BIG};
    #pragma unroll 4
    for (int q = 0; q < JCH / 4; ++q) {
        ulonglong2 Xv = X[q], Yv = Y[q], Zv = Z[q], Wv = W[q];
        u64 d01 = fma2(Zv.x, az, fma2(Yv.x, ay, fma2(Xv.x, ax, Wv.x)));
        u64 d23 = fma2(Zv.y, az, fma2(Yv.y, ay, fma2(Xv.y, ax, Wv.y)));
        float l0, h0, l1, h1;
        f2unpack(d01, l0, h0); f2unpack(d23, l1, h1);
        s_top3(l0, C[0], C[1], C[2]); s_top3(h0, C[3], C[4], C[5]);
        s_top3(l1, C[0], C[1], C[2]); s_top3(h1, C[3], C[4], C[5]);
    }
    float R1 = C[0], R2 = C[1], R3 = C[2];
    s_top3(C[3], R1, R2, R3);
    s_top3(C[4], R1, R2, R3);
    s_top3(C[5], R1, R2, R3);

    float nn1, nn2;
    if (cstar == sc) { nn1 = R2; nn2 = fminf(R3, r2); }  // R1 == self, dropped
    else             { nn1 = R1; nn2 = fminf(R2, r2); }

    const float value = (__fadd_rn(nn1, si) + __fadd_rn(nn2, si)) * 0.5f;
    g_value[b * KPTS + i] = value;

    // ---- deterministic partial sum of value over this CTA's 256 points ----
    float pv = value;
    #pragma unroll
    for (int o = 16; o; o >>= 1) pv += __shfl_xor_sync(0xffffffffu, pv, o);
    if ((tid & 31) == 0) sred[tid >> 5] = pv;
    __syncthreads();
    if (tid == 0) {
        float s = 0.0f;
        #pragma unroll
        for (int w = 0; w < TPB_SEL / 32; ++w) s += sred[w];
        g_sum[b * NSEL + blockIdx.x] = s;
    }
}

// ---------------------------------------------------------------------------
// Kernel B1: threshold (mean from precomputed partials + centered-variance
// pass) + stable compaction + tiled gather. grid = 16, 512 threads. No smem
// staging: values read as float4 from g_value, points gathered from L2.
// ---------------------------------------------------------------------------
__global__ __launch_bounds__(TPB_B1)
void sor_compact_gather_kernel(const float* __restrict__ x,
                               float* __restrict__ out) {
    __shared__ int   skept[KPTS];
    __shared__ float red[NWARP_B];
    __shared__ int   wofs[NWARP_B];
    __shared__ float s_mean, s_thr;
    __shared__ int   s_n;

    const int b    = blockIdx.x;
    const int tid  = threadIdx.x;
    const int lane = tid & 31;
    const int warp = tid >> 5;
    const float* __restrict__ xb = x + b * 3 * KPTS;
    float* __restrict__ ob = out + b * 3 * KPTS;

    // ---- mean from 8 deterministic partials ----
    if (tid == 0) {
        float s = 0.0f;
        #pragma unroll
        for (int k = 0; k < NSEL; ++k) s += g_sum[b * NSEL + k];
        s_mean = s * (1.0f / (float)KPTS);
    }

    // ---- my 4 contiguous values (one float4, coalesced) ----
    const float4 v4 = *reinterpret_cast<const float4*>(
        g_value + b * KPTS + tid * ELEMS_B);
    float v[ELEMS_B] = {v4.x, v4.y, v4.z, v4.w};
    __syncthreads();
    const float mean = s_mean;

    // ---- centered sumsq (ddof = 1) ----
    float s2 = 0.0f;
    #pragma unroll
    for (int u = 0; u < ELEMS_B; ++u) {
        float d = v[u] - mean;
        s2 = __fmaf_rn(d, d, s2);
    }
    #pragma unroll
    for (int o = 16; o; o >>= 1) s2 += __shfl_xor_sync(0xffffffffu, s2, o);
    if (lane == 0) red[warp] = s2;
    __syncthreads();
    if (warp == 0) {
        float t = (lane < NWARP_B) ? red[lane] : 0.0f;
        #pragma unroll
        for (int o = 8; o; o >>= 1) t += __shfl_xor_sync(0xffffffffu, t, o);
        if (lane == 0) {
            float var = t / (float)(KPTS - 1);
            s_thr = __fadd_rn(s_mean, __fmul_rn(1.1f, sqrtf(var)));
        }
    }
    __syncthreads();
    const float thr = s_thr;

    // ---- stable compaction (thread owns 4 contiguous indices) ----
    const int base_t = tid * ELEMS_B;
    unsigned mbits = 0;
    int c = 0;
    #pragma unroll
    for (int u = 0; u < ELEMS_B; ++u) {
        bool m = v[u] <= thr;
        mbits |= (unsigned)m << u;
        c += (int)m;
    }
    int pv = c;
    #pragma unroll
    for (int o = 1; o < 32; o <<= 1) {
        int t2 = __shfl_up_sync(0xffffffffu, pv, o);
        if (lane >= o) pv += t2;
    }
    if (lane == 31) wofs[warp] = pv;
    __syncthreads();
    if (warp == 0) {
        int wv = (lane < NWARP_B) ? wofs[lane] : 0;
        int inc = wv;
        #pragma unroll
        for (int o = 1; o < 32; o <<= 1) {
            int t3 = __shfl_up_sync(0xffffffffu, inc, o);
            if (lane >= o) inc += t3;
        }
        if (lane < NWARP_B) wofs[lane] = inc - wv;
        if (lane == NWARP_B - 1) s_n = inc;
    }
    __syncthreads();
    int pos = (pv - c) + wofs[warp];
    #pragma unroll
    for (int u = 0; u < ELEMS_B; ++u) {
        if ((mbits >> u) & 1u) skept[pos++] = base_t + u;
    }
    __syncthreads();

    // ---- tiled gather straight from global (L2-resident) ----
    const int n = s_n;   // >= 1 always
    #pragma unroll
    for (int j = tid; j < NPOINT; j += TPB_B1) {
        int p = (j < n) ? j : (j % n);
        int idx = skept[p];
        ob[j]            = __ldg(xb + idx);
        ob[KPTS + j]     = __ldg(xb + KPTS + idx);
        ob[2 * KPTS + j] = __ldg(xb + 2 * KPTS + idx);
    }
}

extern "C" void kernel_launch(void* const* d_in, const int* in_sizes, int n_in,
                              void* d_out, int out_size) {
    (void)in_sizes; (void)n_in; (void)out_size;
    const float* x = (const float*)d_in[0];
    float* out = (float*)d_out;

    sor_chunkmin_kernel<<<dim3(NI_CH, JS, BATCH), TPB_A>>>(x);
    sor_select_kernel<<<dim3(NSEL, BATCH), TPB_SEL>>>(x);
    sor_compact_gather_kernel<<<BATCH, TPB_B1>>>(x, out);
}

// round 17
// speedup vs baseline: 1.1222x; 1.0365x over previous
#include <cuda_runtime.h>

#define BATCH   16
#define KPTS    2048
#define NPOINT  2048

#define TPB_A   128
#define IBLK    4
#define ICHUNK  (TPB_A * IBLK)        // 512 i-points per CTA (4 per thread)
#define NI_CH   (KPTS / ICHUNK)       // 4
#define JS      16                    // j-chunks
#define JCH     (KPTS / JS)           // 128

#define TPB_SEL 256
#define NSEL    (KPTS / TPB_SEL)      // 8 CTAs per batch
#define CPAD    132                   // floats per chunk row in A2 smem (128+4)

#define TPB_B1  512
#define NWARP_B (TPB_B1 / 32)         // 16
#define ELEMS_B (KPTS / TPB_B1)       // 4
#define NQ_B    4                     // B1 CTAs per batch (output quarters)
#define QLEN    (NPOINT / NQ_B)       // 512 outputs per CTA
#define FLT_BIG 3.402823466e38f

typedef unsigned long long u64;

// per-(batch, chunk, i) chunk-min distance (d' domain, self excluded)
__device__ float g_min[BATCH * JS * KPTS];
__device__ float g_value[BATCH * KPTS];
__device__ float g_sum[BATCH * NSEL];    // per-A2-CTA partial sums of value

// ---- packed f32x2 helpers ---------------------------------------------------
__device__ __forceinline__ u64 f2pack(float lo, float hi) {
    u64 r; asm("mov.b64 %0, {%1, %2};" : "=l"(r) : "f"(lo), "f"(hi)); return r;
}
__device__ __forceinline__ u64 fma2(u64 a, u64 b, u64 c) {
    u64 d; asm("fma.rn.f32x2 %0, %1, %2, %3;" : "=l"(d) : "l"(a), "l"(b), "l"(c));
    return d;
}
__device__ __forceinline__ void f2unpack(u64 v, float& lo, float& hi) {
    asm("mov.b64 {%0, %1}, %2;" : "=f"(lo), "=f"(hi) : "l"(v));
}
__device__ __forceinline__ void s_top2(float c, float& m1, float& m2) {
    float t = fmaxf(m1, c); m1 = fminf(m1, c); m2 = fminf(m2, t);
}
__device__ __forceinline__ void s_top3(float c, float& m1, float& m2, float& m3) {
    float t1 = fmaxf(m1, c); m1 = fminf(m1, c);
    float t2 = fmaxf(m2, t1); m2 = fminf(m2, t1); m3 = fminf(m3, t2);
}

// ---- A1 chunk scan: 4 accumulators, min-only, double-buffered LDS -----------
template<int SELF>
__device__ __forceinline__ void scan_min4(
    const ulonglong2* __restrict__ px2, const ulonglong2* __restrict__ py2,
    const ulonglong2* __restrict__ pz2, const ulonglong2* __restrict__ pw2,
    const u64* ax, const u64* ay, const u64* az,
    float* out)
{
    float a1[IBLK], a2[IBLK], a3[IBLK], a4[IBLK];
    #pragma unroll
    for (int k = 0; k < IBLK; ++k) {
        a1[k] = FLT_BIG; a2[k] = FLT_BIG; a3[k] = FLT_BIG; a4[k] = FLT_BIG;
    }

    ulonglong2 X = px2[0], Y = py2[0], Z = pz2[0], W = pw2[0];

    #pragma unroll 4
    for (int q = 0; q < JCH / 4; ++q) {
        const int qn = (q + 1 < JCH / 4) ? q + 1 : q;
        ulonglong2 Xn = px2[qn], Yn = py2[qn], Zn = pz2[qn], Wn = pw2[qn];

        #pragma unroll
        for (int k = 0; k < IBLK; ++k) {
            u64 d01 = fma2(Z.x, az[k], fma2(Y.x, ay[k], fma2(X.x, ax[k], W.x)));
            u64 d23 = fma2(Z.y, az[k], fma2(Y.y, ay[k], fma2(X.y, ax[k], W.y)));
            float l0, h0, l1, h1;
            f2unpack(d01, l0, h0); f2unpack(d23, l1, h1);
            if (SELF == k) {
                s_top2(l0, a1[k], a2[k]); s_top2(h0, a3[k], a4[k]);
                s_top2(l1, a1[k], a2[k]); s_top2(h1, a3[k], a4[k]);
            } else {
                a1[k] = fminf(a1[k], fminf(l0, l1));
                a3[k] = fminf(a3[k], fminf(h0, h1));
            }
        }

        X = Xn; Y = Yn; Z = Zn; W = Wn;
    }

    #pragma unroll
    for (int k = 0; k < IBLK; ++k) {
        if (SELF == k)   // union 2nd-smallest of sorted pairs (a1,a2),(a3,a4)
            out[k] = fminf(fmaxf(a1[k], a3[k]), fminf(a2[k], a4[k]));
        else
            out[k] = fminf(a1[k], a3[k]);
    }
}

// ---------------------------------------------------------------------------
// Kernel A1: per-(batch, chunk, i) chunk-min. grid (4, 16, 16) x 128 thr.
// ---------------------------------------------------------------------------
__global__ __launch_bounds__(TPB_A, 7)
void sor_chunkmin_kernel(const float* __restrict__ x) {
    __shared__ __align__(16) float spx[JCH];
    __shared__ __align__(16) float spy[JCH];
    __shared__ __align__(16) float spz[JCH];
    __shared__ __align__(16) float spw[JCH];

    const int b   = blockIdx.z;
    const int ci  = blockIdx.x;
    const int cj  = blockIdx.y;
    const int tid = threadIdx.x;
    const float* __restrict__ xb = x + b * 3 * KPTS;

    {   // stage j-chunk in SoA (JCH == TPB_A)
        int g = cj * JCH + tid;
        float px = xb[g];
        float py = xb[KPTS + g];
        float pz = xb[2 * KPTS + g];
        float sq = __fadd_rn(__fadd_rn(__fmul_rn(px, px), __fmul_rn(py, py)),
                             __fmul_rn(pz, pz));
        spx[tid] = px; spy[tid] = py; spz[tid] = pz; spw[tid] = sq;
    }
    __syncthreads();

    u64 ax[IBLK], ay[IBLK], az[IBLK];
    int ibase = ci * ICHUNK + tid;
    #pragma unroll
    for (int k = 0; k < IBLK; ++k) {
        int ik = ibase + k * TPB_A;
        float xv = xb[ik], yv = xb[KPTS + ik], zv = xb[2 * KPTS + ik];
        ax[k] = f2pack(-2.0f * xv, -2.0f * xv);
        ay[k] = f2pack(-2.0f * yv, -2.0f * yv);
        az[k] = f2pack(-2.0f * zv, -2.0f * zv);
    }

    const ulonglong2* px2 = reinterpret_cast<const ulonglong2*>(spx);
    const ulonglong2* py2 = reinterpret_cast<const ulonglong2*>(spy);
    const ulonglong2* pz2 = reinterpret_cast<const ulonglong2*>(spz);
    const ulonglong2* pw2 = reinterpret_cast<const ulonglong2*>(spw);

    float out[IBLK];
    const int selfk = cj - 4 * ci;    // in [0,4) iff some acc's self is here
    switch (selfk) {
        case 0:  scan_min4<0>(px2, py2, pz2, pw2, ax, ay, az, out); break;
        case 1:  scan_min4<1>(px2, py2, pz2, pw2, ax, ay, az, out); break;
        case 2:  scan_min4<2>(px2, py2, pz2, pw2, ax, ay, az, out); break;
        case 3:  scan_min4<3>(px2, py2, pz2, pw2, ax, ay, az, out); break;
        default: scan_min4<-1>(px2, py2, pz2, pw2, ax, ay, az, out); break;
    }

    float* __restrict__ gm = g_min + (b * JS + cj) * KPTS;
    #pragma unroll
    for (int k = 0; k < IBLK; ++k) gm[ibase + k * TPB_A] = out[k];
}

// ---------------------------------------------------------------------------
// Kernel A2: exact top-2 recovery + per-CTA partial sum of value.
// grid (8, 16) = 128 CTAs x 256 thr (proven R16 version, unchanged).
// ---------------------------------------------------------------------------
__global__ __launch_bounds__(TPB_SEL)
void sor_select_kernel(const float* __restrict__ x) {
    __shared__ __align__(16) float sxp[JS * CPAD];
    __shared__ __align__(16) float syp[JS * CPAD];
    __shared__ __align__(16) float szp[JS * CPAD];
    __shared__ __align__(16) float swp[JS * CPAD];
    __shared__ float sred[TPB_SEL / 32];

    const int b   = blockIdx.y;
    const int tid = threadIdx.x;
    const int i   = blockIdx.x * TPB_SEL + tid;
    const float* __restrict__ xb = x + b * 3 * KPTS;

    for (int idx = tid; idx < KPTS; idx += TPB_SEL) {
        int c = idx >> 7, e = idx & 127;
        float px = xb[idx];
        float py = xb[KPTS + idx];
        float pz = xb[2 * KPTS + idx];
        float sq = __fadd_rn(__fadd_rn(__fmul_rn(px, px), __fmul_rn(py, py)),
                             __fmul_rn(pz, pz));
        int off = c * CPAD + e;
        sxp[off] = px; syp[off] = py; szp[off] = pz; swp[off] = sq;
    }
    __syncthreads();

    // ---- chunk mins -> m1, cstar, r2 ----
    float m1 = FLT_BIG, r2 = FLT_BIG;
    int cstar = 0;
    #pragma unroll
    for (int c = 0; c < JS; ++c) {
        float v = g_min[(b * JS + c) * KPTS + i];
        if (v < m1) { r2 = m1; m1 = v; cstar = c; }
        else        { r2 = fminf(r2, v); }
    }

    // ---- own point data ----
    const int sc = i >> 7;
    const int se = i & 127;
    const int ob = sc * CPAD + se;
    const float xi = sxp[ob], yi = syp[ob], zi = szp[ob], si = swp[ob];
    const u64 ax = f2pack(-2.0f * xi, -2.0f * xi);
    const u64 ay = f2pack(-2.0f * yi, -2.0f * yi);
    const u64 az = f2pack(-2.0f * zi, -2.0f * zi);

    // ---- rescan chunk cstar with top-3 dual chains (self included) ----
    const ulonglong2* X = reinterpret_cast<const ulonglong2*>(sxp + cstar * CPAD);
    const ulonglong2* Y = reinterpret_cast<const ulonglong2*>(syp + cstar * CPAD);
    const ulonglong2* Z = reinterpret_cast<const ulonglong2*>(szp + cstar * CPAD);
    const ulonglong2* W = reinterpret_cast<const ulonglong2*>(swp + cstar * CPAD);

    float C[6] = {FLT_BIG, FLT_BIG, FLT_BIG, FLT_BIG, FLT_BIG, FLT_BIG};
    #pragma unroll 4
    for (int q = 0; q < JCH / 4; ++q) {
        ulonglong2 Xv = X[q], Yv = Y[q], Zv = Z[q], Wv = W[q];
        u64 d01 = fma2(Zv.x, az, fma2(Yv.x, ay, fma2(Xv.x, ax, Wv.x)));
        u64 d23 = fma2(Zv.y, az, fma2(Yv.y, ay, fma2(Xv.y, ax, Wv.y)));
        float l0, h0, l1, h1;
        f2unpack(d01, l0, h0); f2unpack(d23, l1, h1);
        s_top3(l0, C[0], C[1], C[2]); s_top3(h0, C[3], C[4], C[5]);
        s_top3(l1, C[0], C[1], C[2]); s_top3(h1, C[3], C[4], C[5]);
    }
    float R1 = C[0], R2 = C[1], R3 = C[2];
    s_top3(C[3], R1, R2, R3);
    s_top3(C[4], R1, R2, R3);
    s_top3(C[5], R1, R2, R3);

    float nn1, nn2;
    if (cstar == sc) { nn1 = R2; nn2 = fminf(R3, r2); }  // R1 == self, dropped
    else             { nn1 = R1; nn2 = fminf(R2, r2); }

    const float value = (__fadd_rn(nn1, si) + __fadd_rn(nn2, si)) * 0.5f;
    g_value[b * KPTS + i] = value;

    // ---- deterministic partial sum of value over this CTA's 256 points ----
    float pv = value;
    #pragma unroll
    for (int o = 16; o; o >>= 1) pv += __shfl_xor_sync(0xffffffffu, pv, o);
    if ((tid & 31) == 0) sred[tid >> 5] = pv;
    __syncthreads();
    if (tid == 0) {
        float s = 0.0f;
        #pragma unroll
        for (int w = 0; w < TPB_SEL / 32; ++w) s += sred[w];
        g_sum[b * NSEL + blockIdx.x] = s;
    }
}

// ---------------------------------------------------------------------------
// Kernel B1: threshold + stable compaction (redundant per CTA) + gather of
// one output quarter. grid (4, 16) = 64 CTAs x 512 thr.
// ---------------------------------------------------------------------------
__global__ __launch_bounds__(TPB_B1)
void sor_compact_gather_kernel(const float* __restrict__ x,
                               float* __restrict__ out) {
    __shared__ float sx[KPTS];
    __shared__ float sy[KPTS];
    __shared__ float sz[KPTS];
    __shared__ int   skept[KPTS];
    __shared__ float red[NWARP_B];
    __shared__ int   wofs[NWARP_B];
    __shared__ float s_mean, s_thr;
    __shared__ int   s_n;

    const int qtr  = blockIdx.x;     // output quarter
    const int b    = blockIdx.y;
    const int tid  = threadIdx.x;
    const int lane = tid & 31;
    const int warp = tid >> 5;
    const float* __restrict__ xb = x + b * 3 * KPTS;
    float* __restrict__ ob = out + b * 3 * KPTS;

    // ---- stage points (coalesced) ----
    #pragma unroll
    for (int t = tid; t < KPTS; t += TPB_B1) {
        sx[t] = xb[t];
        sy[t] = xb[KPTS + t];
        sz[t] = xb[2 * KPTS + t];
    }

    // ---- mean from 8 deterministic partials ----
    if (tid == 0) {
        float s = 0.0f;
        #pragma unroll
        for (int k = 0; k < NSEL; ++k) s += g_sum[b * NSEL + k];
        s_mean = s * (1.0f / (float)KPTS);
    }

    // ---- my 4 contiguous values (one float4, coalesced) ----
    const float4 v4 = *reinterpret_cast<const float4*>(
        g_value + b * KPTS + tid * ELEMS_B);
    float v[ELEMS_B] = {v4.x, v4.y, v4.z, v4.w};
    __syncthreads();
    const float mean = s_mean;

    // ---- centered sumsq (ddof = 1) ----
    float s2 = 0.0f;
    #pragma unroll
    for (int u = 0; u < ELEMS_B; ++u) {
        float d = v[u] - mean;
        s2 = __fmaf_rn(d, d, s2);
    }
    #pragma unroll
    for (int o = 16; o; o >>= 1) s2 += __shfl_xor_sync(0xffffffffu, s2, o);
    if (lane == 0) red[warp] = s2;
    __syncthreads();
    if (warp == 0) {
        float t = (lane < NWARP_B) ? red[lane] : 0.0f;
        #pragma unroll
        for (int o = 8; o; o >>= 1) t += __shfl_xor_sync(0xffffffffu, t, o);
        if (lane == 0) {
            float var = t / (float)(KPTS - 1);
            s_thr = __fadd_rn(s_mean, __fmul_rn(1.1f, sqrtf(var)));
        }
    }
    __syncthreads();
    const float thr = s_thr;

    // ---- stable compaction (thread owns 4 contiguous indices) ----
    const int base_t = tid * ELEMS_B;
    unsigned mbits = 0;
    int c = 0;
    #pragma unroll
    for (int u = 0; u < ELEMS_B; ++u) {
        bool m = v[u] <= thr;
        mbits |= (unsigned)m << u;
        c += (int)m;
    }
    int pv = c;
    #pragma unroll
    for (int o = 1; o < 32; o <<= 1) {
        int t2 = __shfl_up_sync(0xffffffffu, pv, o);
        if (lane >= o) pv += t2;
    }
    if (lane == 31) wofs[warp] = pv;
    __syncthreads();
    if (warp == 0) {
        int wv = (lane < NWARP_B) ? wofs[lane] : 0;
        int inc = wv;
        #pragma unroll
        for (int o = 1; o < 32; o <<= 1) {
            int t3 = __shfl_up_sync(0xffffffffu, inc, o);
            if (lane >= o) inc += t3;
        }
        if (lane < NWARP_B) wofs[lane] = inc - wv;
        if (lane == NWARP_B - 1) s_n = inc;
    }
    __syncthreads();
    int pos = (pv - c) + wofs[warp];
    #pragma unroll
    for (int u = 0; u < ELEMS_B; ++u) {
        if ((mbits >> u) & 1u) skept[pos++] = base_t + u;
    }
    __syncthreads();

    // ---- gather my quarter: one output per thread ----
    const int n = s_n;   // >= 1 always
    const int j = qtr * QLEN + tid;
    int p = (j < n) ? j : (j % n);
    int idx = skept[p];
    ob[j]            = sx[idx];
    ob[KPTS + j]     = sy[idx];
    ob[2 * KPTS + j] = sz[idx];
}

extern "C" void kernel_launch(void* const* d_in, const int* in_sizes, int n_in,
                              void* d_out, int out_size) {
    (void)in_sizes; (void)n_in; (void)out_size;
    const float* x = (const float*)d_in[0];
    float* out = (float*)d_out;

    sor_chunkmin_kernel<<<dim3(NI_CH, JS, BATCH), TPB_A>>>(x);
    sor_select_kernel<<<dim3(NSEL, BATCH), TPB_SEL>>>(x);
    sor_compact_gather_kernel<<<dim3(NQ_B, BATCH), TPB_B1>>>(x, out);
}